// round 15
// baseline (speedup 1.0000x reference)
#include <cuda_runtime.h>
#include <cuda_fp16.h>
#include <math.h>
#include <stdint.h>

#define BB 2048
#define TT 128
#define VV 25
#define HH 512
#define NC 100

// int8 step kernel
#define NCH 16
#define ROWB8 48
#define TILE8 (128 * ROWB8)
#define STAGE8 (4 * TILE8)          // A1,A2,W1,W2
#define XPROW 528                   // 512B row + 16B pad
#define XPOFF (2 * STAGE8)          // 49152
#define SMEM8 (XPOFF + 128 * XPROW) // 116736
// xproj kernel (fp16)
#define ROWB16 80
#define TILE16 (128 * ROWB16)
#define SMEM16 (4 * TILE16)         // 40960

__device__ __align__(1024) signed char g_W1[2048][512];
__device__ __align__(1024) signed char g_W2[2048][512];
__device__ __align__(1024) signed char g_hA1[2][BB][HH];
__device__ __align__(1024) signed char g_hA2[2][BB][HH];
__device__ __align__(1024) float g_c[(size_t)HH * BB];
__device__ float g_bias[2048];
__device__ __align__(1024) __half g_x_hi[TT][BB][32];
__device__ __align__(1024) __half g_x_lo[TT][BB][32];
__device__ __align__(1024) __half g_Wih_hi[2048][32];
__device__ __align__(1024) __half g_Wih_lo[2048][32];
__device__ float g_xpA[(size_t)64 * 2048 * 2048];   // xproj t<64
__device__ float g_xpB[(size_t)64 * 2048 * 2048];   // xproj t>=64

__device__ __forceinline__ uint32_t s2u(const void* p) {
    uint32_t a;
    asm("{ .reg .u64 t; cvta.to.shared.u64 t, %1; cvt.u32.u64 %0, t; }" : "=r"(a) : "l"(p));
    return a;
}
__device__ __forceinline__ void ldsm4(uint32_t (&r)[4], uint32_t addr) {
    asm volatile("ldmatrix.sync.aligned.m8n8.x4.shared.b16 {%0,%1,%2,%3}, [%4];"
        : "=r"(r[0]), "=r"(r[1]), "=r"(r[2]), "=r"(r[3]) : "r"(addr));
}
__device__ __forceinline__ void mma16816(float (&d)[4], const uint32_t (&a)[4],
                                         uint32_t b0, uint32_t b1) {
    asm volatile("mma.sync.aligned.m16n8k16.row.col.f32.f16.f16.f32 "
        "{%0,%1,%2,%3}, {%4,%5,%6,%7}, {%8,%9}, {%0,%1,%2,%3};"
        : "+f"(d[0]), "+f"(d[1]), "+f"(d[2]), "+f"(d[3])
        : "r"(a[0]), "r"(a[1]), "r"(a[2]), "r"(a[3]), "r"(b0), "r"(b1));
}
__device__ __forceinline__ void imma(int (&d)[4], const uint32_t (&a)[4],
                                     uint32_t b0, uint32_t b1) {
    asm volatile("mma.sync.aligned.m16n8k32.row.col.s32.s8.s8.s32 "
        "{%0,%1,%2,%3}, {%4,%5,%6,%7}, {%8,%9}, {%0,%1,%2,%3};"
        : "+r"(d[0]), "+r"(d[1]), "+r"(d[2]), "+r"(d[3])
        : "r"(a[0]), "r"(a[1]), "r"(a[2]), "r"(a[3]), "r"(b0), "r"(b1));
}
__device__ __forceinline__ void cpasync16(uint32_t dst, const void* src) {
    size_t g = __cvta_generic_to_global(src);
    asm volatile("cp.async.cg.shared.global [%0], [%1], 16;" :: "r"(dst), "l"(g));
}
__device__ __forceinline__ float fsig(float x) { return 1.0f / (1.0f + __expf(-x)); }
__device__ __forceinline__ float ftanh_(float x) {
    float e = __expf(2.0f * x);
    return 1.0f - 2.0f / (e + 1.0f);
}
__device__ __forceinline__ int q8(float v, float s) {
    int q = __float2int_rn(v * s);
    return max(-127, min(127, q));
}

// ---- prep ----
__global__ void prep_w(const float* __restrict__ W_hh,
                       const float* __restrict__ b_ih, const float* __restrict__ b_hh) {
    int idx = blockIdx.x * blockDim.x + threadIdx.x;
    if (idx >= 2048 * 512) return;
    int C = idx >> 9, k = idx & 511;
    int orig = (C & 3) * HH + (C >> 2);
    float w = W_hh[(size_t)orig * HH + k];
    int q1 = q8(w, 256.0f);
    int q2 = q8(w - q1 * (1.0f / 256.0f), 32768.0f);
    g_W1[C][k] = (signed char)q1;
    g_W2[C][k] = (signed char)q2;
    if (k == 0) g_bias[C] = b_ih[orig] + b_hh[orig];
}
__global__ void prep_wih(const float* __restrict__ W_ih) {
    int idx = blockIdx.x * blockDim.x + threadIdx.x;
    if (idx >= 2048 * 32) return;
    int C = idx >> 5, k = idx & 31;
    int orig = (C & 3) * HH + (C >> 2);
    float v = (k < VV) ? W_ih[(size_t)orig * VV + k] : 0.0f;
    __half hi = __float2half(v);
    g_Wih_hi[C][k] = hi;
    g_Wih_lo[C][k] = __float2half(v - __half2float(hi));
}
__global__ void prep_x(const float* __restrict__ msgs) {
    int idx = blockIdx.x * blockDim.x + threadIdx.x;
    if (idx >= TT * BB * 32) return;
    int kk = idx & 31, rt = idx >> 5;
    int row = rt & (BB - 1), t = rt >> 11;
    float v = (kk < VV) ? msgs[((size_t)row * TT + t) * VV + kk] : 0.0f;
    __half hi = __float2half(v);
    g_x_hi[t][row][kk] = hi;
    g_x_lo[t][row][kk] = __float2half(v - __half2float(hi));
}
__global__ void init_state() {
    size_t i = (size_t)blockIdx.x * blockDim.x + threadIdx.x;
    if (i < (size_t)BB * HH) {
        g_hA1[0][0][i] = 0; g_hA2[0][0][i] = 0; g_c[i] = 0.0f;
    }
}

// ---- xproj: K=32 fp16-split HMMA, writes xp[t][row][C] = x@Wih^T + bias ----
__global__ __launch_bounds__(256, 2) void xproj_kernel(float* __restrict__ xp, int t0) {
    extern __shared__ __align__(1024) char smem[];
    const uint32_t sb = s2u(smem);
    const int tid = threadIdx.x, wid = tid >> 5, lane = tid & 31;
    const int wm = wid & 1, wn = wid >> 1;
    const int row0 = blockIdx.x * 128, C0 = blockIdx.y * 128;
    const int t = t0 + blockIdx.z;

    #pragma unroll
    for (int i = 0; i < 8; i++) {
        int p = tid + i * 256;
        int tile = p >> 9, r = (p >> 2) & 127, cc = p & 3;
        uint32_t dst = sb + tile * TILE16 + r * ROWB16 + cc * 16;
        const void* src;
        if (tile == 0)      src = &g_x_hi[t][row0 + r][cc * 8];
        else if (tile == 1) src = &g_x_lo[t][row0 + r][cc * 8];
        else if (tile == 2) src = &g_Wih_hi[C0 + r][cc * 8];
        else                src = &g_Wih_lo[C0 + r][cc * 8];
        cpasync16(dst, src);
    }
    asm volatile("cp.async.commit_group;");
    asm volatile("cp.async.wait_group 0;");
    __syncthreads();

    float d[4][4][4];
    #pragma unroll
    for (int a = 0; a < 4; a++)
        #pragma unroll
        for (int b = 0; b < 4; b++)
            #pragma unroll
            for (int c = 0; c < 4; c++) d[a][b][c] = 0.0f;

    const uint32_t b_lane = (wn * 32 + ((lane >> 4) & 1) * 8 + (lane & 7)) * ROWB16
                          + ((lane >> 3) & 1) * 16 + 2 * TILE16;
    const uint32_t a_lane = (wm * 64 + (lane & 15)) * ROWB16 + (lane >> 4) * 16;

    #pragma unroll
    for (int k16 = 0; k16 < 2; k16++) {
        const uint32_t kb = k16 * 32;
        uint32_t bh[4][2], bl[4][2];
        #pragma unroll
        for (int g16 = 0; g16 < 2; g16++) {
            uint32_t ba = sb + b_lane + g16 * (16 * ROWB16) + kb;
            uint32_t r4[4];
            ldsm4(r4, ba);
            bh[g16*2+0][0] = r4[0]; bh[g16*2+0][1] = r4[1];
            bh[g16*2+1][0] = r4[2]; bh[g16*2+1][1] = r4[3];
            ldsm4(r4, ba + TILE16);
            bl[g16*2+0][0] = r4[0]; bl[g16*2+0][1] = r4[1];
            bl[g16*2+1][0] = r4[2]; bl[g16*2+1][1] = r4[3];
        }
        uint32_t ah[4][4], al[4][4];
        #pragma unroll
        for (int mf = 0; mf < 4; mf++) {
            uint32_t aa = sb + a_lane + mf * (16 * ROWB16) + kb;
            ldsm4(ah[mf], aa);
            ldsm4(al[mf], aa + TILE16);
        }
        #pragma unroll
        for (int mf = 0; mf < 4; mf++)
            #pragma unroll
            for (int nf = 0; nf < 4; nf++) {
                mma16816(d[mf][nf], ah[mf], bh[nf][0], bh[nf][1]);
                mma16816(d[mf][nf], ah[mf], bl[nf][0], bl[nf][1]);
                mma16816(d[mf][nf], al[mf], bh[nf][0], bh[nf][1]);
            }
    }

    float* o = xp + (size_t)blockIdx.z * 2048 * 2048;
    const int g = lane >> 2, tig = lane & 3;
    #pragma unroll
    for (int nf = 0; nf < 4; nf++) {
        int Cc = C0 + wn * 32 + nf * 8 + 2 * tig;
        float b0 = g_bias[Cc], b1 = g_bias[Cc + 1];
        #pragma unroll
        for (int mf = 0; mf < 4; mf++) {
            int rg = row0 + wm * 64 + mf * 16 + g;
            *(float2*)&o[(size_t)rg * 2048 + Cc] =
                make_float2(d[mf][nf][0] + b0, d[mf][nf][1] + b1);
            *(float2*)&o[(size_t)(rg + 8) * 2048 + Cc] =
                make_float2(d[mf][nf][2] + b0, d[mf][nf][3] + b1);
        }
    }
}

// ---- int8 producer: 4 tiles x 128 rows x 2x16B / 512 thr = 2 iters ----
__device__ __forceinline__ void produce8(uint32_t sb, int st, int kc, int hb,
                                         int row0, int C0, int tid) {
    #pragma unroll
    for (int i = 0; i < 2; i++) {
        int p = tid + i * 512;
        int tile = p >> 8, r = (p >> 1) & 127, hf = p & 1;
        int ko = kc * 32 + hf * 16;
        uint32_t dst = sb + st * STAGE8 + tile * TILE8 + r * ROWB8 + hf * 16;
        const void* src;
        if (tile == 0)      src = &g_hA1[hb][row0 + r][ko];
        else if (tile == 1) src = &g_hA2[hb][row0 + r][ko];
        else if (tile == 2) src = &g_W1[C0 + r][ko];
        else                src = &g_W2[C0 + r][ko];
        cpasync16(dst, src);
    }
}

// ---- int8 LSTM step ----
__global__ __launch_bounds__(512, 1) void lstm_step_i8(const float* __restrict__ xp, int t) {
    extern __shared__ __align__(1024) char smem[];
    const uint32_t sb = s2u(smem);
    const int tid = threadIdx.x, wid = tid >> 5, lane = tid & 31;
    const int wm = wid & 3, wn = wid >> 2;        // warp tile 32x32
    const int row0 = blockIdx.x * 128, C0 = blockIdx.y * 128;
    const int hb = t & 1, nb = (t + 1) & 1;

    int S1[2][4][4], Sc[2][4][4];
    #pragma unroll
    for (int a = 0; a < 2; a++)
        #pragma unroll
        for (int b = 0; b < 4; b++)
            #pragma unroll
            for (int c = 0; c < 4; c++) { S1[a][b][c] = 0; Sc[a][b][c] = 0; }

    // chunk 0 + xp tile prefetch in ONE group: xp load overlaps the whole mainloop ramp
    produce8(sb, 0, 0, hb, row0, C0, tid);
    #pragma unroll
    for (int i = 0; i < 8; i++) {
        int p = tid + i * 512;
        int r = p >> 5, c = p & 31;
        cpasync16(sb + XPOFF + r * XPROW + c * 16,
                  (const void*)(xp + (size_t)(row0 + r) * 2048 + C0 + c * 4));
    }
    asm volatile("cp.async.commit_group;");

    const uint32_t b_lane = (wn * 32 + ((lane >> 3) & 1) * 8 + (lane & 7)) * ROWB8
                          + ((lane >> 4) & 1) * 16 + 2 * TILE8;
    const uint32_t a_lane = ((lane & 7) + ((lane >> 3) & 1) * 8 + wm * 32) * ROWB8
                          + ((lane >> 4) & 1) * 16;

    for (int kc = 0; kc < NCH; kc++) {
        asm volatile("cp.async.wait_group 0;");
        __syncthreads();
        if (kc + 1 < NCH) {
            produce8(sb, (kc + 1) & 1, kc + 1, hb, row0, C0, tid);
            asm volatile("cp.async.commit_group;");
        }
        const uint32_t st = sb + (kc & 1) * STAGE8;
        uint32_t w1[4][2], w2[4][2];
        #pragma unroll
        for (int g16 = 0; g16 < 2; g16++) {
            uint32_t ba = st + b_lane + g16 * (16 * ROWB8);
            uint32_t r4[4];
            ldsm4(r4, ba);                 // W1
            w1[g16*2+0][0] = r4[0]; w1[g16*2+0][1] = r4[2];
            w1[g16*2+1][0] = r4[1]; w1[g16*2+1][1] = r4[3];
            ldsm4(r4, ba + TILE8);         // W2
            w2[g16*2+0][0] = r4[0]; w2[g16*2+0][1] = r4[2];
            w2[g16*2+1][0] = r4[1]; w2[g16*2+1][1] = r4[3];
        }
        uint32_t a1[2][4], a2[2][4];
        #pragma unroll
        for (int mf = 0; mf < 2; mf++) {
            uint32_t aa = st + a_lane + mf * (16 * ROWB8);
            ldsm4(a1[mf], aa);
            ldsm4(a2[mf], aa + TILE8);
        }
        #pragma unroll
        for (int mf = 0; mf < 2; mf++)
            #pragma unroll
            for (int nf = 0; nf < 4; nf++)
                imma(S1[mf][nf], a1[mf], w1[nf][0], w1[nf][1]);
        #pragma unroll
        for (int mf = 0; mf < 2; mf++)
            #pragma unroll
            for (int nf = 0; nf < 4; nf++)
                imma(Sc[mf][nf], a1[mf], w2[nf][0], w2[nf][1]);
        #pragma unroll
        for (int mf = 0; mf < 2; mf++)
            #pragma unroll
            for (int nf = 0; nf < 4; nf++)
                imma(Sc[mf][nf], a2[mf], w1[nf][0], w1[nf][1]);
    }

    // ---- fused epilogue (xp from smem) ----
    const float s1 = 1.0f / 32768.0f, sc = 1.0f / 4194304.0f;
    const int g = lane >> 2, tig = lane & 3;
    #pragma unroll
    for (int nf = 0; nf < 4; nf++) {
        int Cl = wn * 32 + nf * 8 + 2 * tig;
        int j = (C0 >> 2) + wn * 8 + nf * 2 + (tig >> 1);
        #pragma unroll
        for (int mf = 0; mf < 2; mf++) {
            int rl = wm * 32 + mf * 16 + g;
            float2 xp01 = *(const float2*)(smem + XPOFF + rl * XPROW + Cl * 4);
            float2 xp23 = *(const float2*)(smem + XPOFF + (rl + 8) * XPROW + Cl * 4);
            float c0 = (float)S1[mf][nf][0] * s1 + (float)Sc[mf][nf][0] * sc + xp01.x;
            float c1 = (float)S1[mf][nf][1] * s1 + (float)Sc[mf][nf][1] * sc + xp01.y;
            float c2 = (float)S1[mf][nf][2] * s1 + (float)Sc[mf][nf][2] * sc + xp23.x;
            float c3 = (float)S1[mf][nf][3] * s1 + (float)Sc[mf][nf][3] * sc + xp23.y;
            float s0 = __shfl_xor_sync(0xFFFFFFFFu, c0, 1);
            float sA = __shfl_xor_sync(0xFFFFFFFFu, c1, 1);
            float sB = __shfl_xor_sync(0xFFFFFFFFu, c2, 1);
            float sC = __shfl_xor_sync(0xFFFFFFFFu, c3, 1);
            int row;
            float gi, gf, gg, go;
            if (!(tig & 1)) {
                row = row0 + rl;
                gi = c0; gf = c1; gg = s0; go = sA;
            } else {
                row = row0 + rl + 8;
                gi = sB; gf = sC; gg = c2; go = c3;
            }
            gi = fsig(gi); gf = fsig(gf); gg = ftanh_(gg); go = fsig(go);
            size_t ci = (size_t)j * BB + row;
            float cn = gf * g_c[ci] + gi * gg;
            g_c[ci] = cn;
            float h = go * ftanh_(cn);
            int A1 = q8(h, 128.0f);
            int A2 = q8(h - A1 * (1.0f / 128.0f), 16384.0f);
            g_hA1[nb][row][j] = (signed char)A1;
            g_hA2[nb][row][j] = (signed char)A2;
        }
    }
}

// ---- final FC ----
__global__ void fc_kernel(const float* __restrict__ W_fc,
                          const float* __restrict__ b_fc,
                          float* __restrict__ out)
{
    __shared__ float hs[HH];
    int b = blockIdx.x;
    for (int k = threadIdx.x; k < HH; k += blockDim.x)
        hs[k] = (float)g_hA1[0][b][k] * (1.0f / 128.0f)
              + (float)g_hA2[0][b][k] * (1.0f / 16384.0f);
    __syncthreads();
    int cls = threadIdx.x;
    if (cls < NC) {
        const float* w = &W_fc[(size_t)cls * HH];
        float acc = 0.0f;
        #pragma unroll 8
        for (int k = 0; k < HH; k++) acc += hs[k] * w[k];
        out[(size_t)b * NC + cls] = acc + b_fc[cls];
    }
}

extern "C" void kernel_launch(void* const* d_in, const int* in_sizes, int n_in,
                              void* d_out, int out_size)
{
    const float* msgs = (const float*)d_in[0];
    const float* W_ih = (const float*)d_in[1];
    const float* W_hh = (const float*)d_in[2];
    const float* b_ih = (const float*)d_in[3];
    const float* b_hh = (const float*)d_in[4];
    const float* W_fc = (const float*)d_in[5];
    const float* b_fc = (const float*)d_in[6];
    float* out = (float*)d_out;

    cudaFuncSetAttribute(xproj_kernel, cudaFuncAttributeMaxDynamicSharedMemorySize, SMEM16);
    cudaFuncSetAttribute(lstm_step_i8, cudaFuncAttributeMaxDynamicSharedMemorySize, SMEM8);

    void *xpA, *xpB;
    cudaGetSymbolAddress(&xpA, g_xpA);
    cudaGetSymbolAddress(&xpB, g_xpB);

    prep_w<<<(2048 * 512 + 255) / 256, 256>>>(W_hh, b_ih, b_hh);
    prep_wih<<<(2048 * 32 + 255) / 256, 256>>>(W_ih);
    prep_x<<<(TT * BB * 32 + 255) / 256, 256>>>(msgs);
    init_state<<<(BB * HH + 255) / 256, 256>>>();

    xproj_kernel<<<dim3(16, 16, 64), 256, SMEM16>>>((float*)xpA, 0);
    xproj_kernel<<<dim3(16, 16, 64), 256, SMEM16>>>((float*)xpB, 64);

    dim3 grid(16, 16);
    for (int t = 0; t < TT; t++) {
        const float* xp_t = (const float*)(t < 64 ? xpA : xpB)
                          + (size_t)(t & 63) * 2048 * 2048;
        lstm_step_i8<<<grid, 512, SMEM8>>>(xp_t, t);
    }
    fc_kernel<<<BB, 128>>>(W_fc, b_fc, out);
}

// round 17
// speedup vs baseline: 2.5856x; 2.5856x over previous
#include <cuda_runtime.h>
#include <cuda_fp16.h>
#include <math.h>
#include <stdint.h>

#define BB 2048
#define TT 128
#define VV 25
#define HH 512
#define NC 100
#define NCH 16            // K=512, 32 per chunk

#define ROWB 80
#define TILE (128 * ROWB)           // 10240
#define STAGE (3 * TILE)            // Ahi, Whi, Wlo = 30720
#define SMEMS (2 * STAGE)           // 61440
// xproj kernel (fp16) smem
#define TILE16 (128 * ROWB)
#define SMEM16 (4 * TILE16)         // 40960

__device__ __align__(1024) __half g_Whi[2048][512];   // permuted C=4j+gate
__device__ __align__(1024) __half g_Wlo[2048][512];
__device__ __align__(1024) __half g_h[2][BB][HH];     // fp16 hidden (hi only)
__device__ __align__(1024) float g_c[(size_t)HH * BB];
__device__ float g_bias[2048];
__device__ __align__(1024) __half g_x_hi[TT][BB][32];
__device__ __align__(1024) __half g_x_lo[TT][BB][32];
__device__ __align__(1024) __half g_Wih_hi[2048][32];
__device__ __align__(1024) __half g_Wih_lo[2048][32];
__device__ float g_xpA[(size_t)64 * 2048 * 2048];
__device__ float g_xpB[(size_t)64 * 2048 * 2048];

__device__ __forceinline__ uint32_t s2u(const void* p) {
    uint32_t a;
    asm("{ .reg .u64 t; cvta.to.shared.u64 t, %1; cvt.u32.u64 %0, t; }" : "=r"(a) : "l"(p));
    return a;
}
__device__ __forceinline__ void ldsm4(uint32_t (&r)[4], uint32_t addr) {
    asm volatile("ldmatrix.sync.aligned.m8n8.x4.shared.b16 {%0,%1,%2,%3}, [%4];"
        : "=r"(r[0]), "=r"(r[1]), "=r"(r[2]), "=r"(r[3]) : "r"(addr));
}
__device__ __forceinline__ void mma16816(float (&d)[4], const uint32_t (&a)[4],
                                         uint32_t b0, uint32_t b1) {
    asm volatile("mma.sync.aligned.m16n8k16.row.col.f32.f16.f16.f32 "
        "{%0,%1,%2,%3}, {%4,%5,%6,%7}, {%8,%9}, {%0,%1,%2,%3};"
        : "+f"(d[0]), "+f"(d[1]), "+f"(d[2]), "+f"(d[3])
        : "r"(a[0]), "r"(a[1]), "r"(a[2]), "r"(a[3]), "r"(b0), "r"(b1));
}
__device__ __forceinline__ void cpasync16(uint32_t dst, const void* src) {
    size_t g = __cvta_generic_to_global(src);
    asm volatile("cp.async.cg.shared.global [%0], [%1], 16;" :: "r"(dst), "l"(g));
}
__device__ __forceinline__ float fsig(float x) { return 1.0f / (1.0f + __expf(-x)); }
__device__ __forceinline__ float ftanh_(float x) {
    float e = __expf(2.0f * x);
    return 1.0f - 2.0f / (e + 1.0f);
}

// ---- prep ----
__global__ void prep_w(const float* __restrict__ W_hh,
                       const float* __restrict__ b_ih, const float* __restrict__ b_hh) {
    int idx = blockIdx.x * blockDim.x + threadIdx.x;
    if (idx >= 2048 * 512) return;
    int C = idx >> 9, k = idx & 511;
    int orig = (C & 3) * HH + (C >> 2);
    float w = W_hh[(size_t)orig * HH + k];
    __half hi = __float2half(w);
    g_Whi[C][k] = hi;
    g_Wlo[C][k] = __float2half(w - __half2float(hi));
    if (k == 0) g_bias[C] = b_ih[orig] + b_hh[orig];
}
__global__ void prep_wih(const float* __restrict__ W_ih) {
    int idx = blockIdx.x * blockDim.x + threadIdx.x;
    if (idx >= 2048 * 32) return;
    int C = idx >> 5, k = idx & 31;
    int orig = (C & 3) * HH + (C >> 2);
    float v = (k < VV) ? W_ih[(size_t)orig * VV + k] : 0.0f;
    __half hi = __float2half(v);
    g_Wih_hi[C][k] = hi;
    g_Wih_lo[C][k] = __float2half(v - __half2float(hi));
}
__global__ void prep_x(const float* __restrict__ msgs) {
    int idx = blockIdx.x * blockDim.x + threadIdx.x;
    if (idx >= TT * BB * 32) return;
    int kk = idx & 31, rt = idx >> 5;
    int row = rt & (BB - 1), t = rt >> 11;
    float v = (kk < VV) ? msgs[((size_t)row * TT + t) * VV + kk] : 0.0f;
    __half hi = __float2half(v);
    g_x_hi[t][row][kk] = hi;
    g_x_lo[t][row][kk] = __float2half(v - __half2float(hi));
}
__global__ void init_state() {
    size_t i = (size_t)blockIdx.x * blockDim.x + threadIdx.x;
    if (i < (size_t)BB * HH) {
        g_h[0][0][i] = __float2half(0.0f);
        g_c[i] = 0.0f;
    }
}

// ---- xproj: K=32 fp16-split HMMA, xp[t][row][C] = x@Wih^T + bias ----
__global__ __launch_bounds__(256, 2) void xproj_kernel(float* __restrict__ xp, int t0) {
    extern __shared__ __align__(1024) char smem[];
    const uint32_t sb = s2u(smem);
    const int tid = threadIdx.x, wid = tid >> 5, lane = tid & 31;
    const int wm = wid & 1, wn = wid >> 1;
    const int row0 = blockIdx.x * 128, C0 = blockIdx.y * 128;
    const int t = t0 + blockIdx.z;

    #pragma unroll
    for (int i = 0; i < 8; i++) {
        int p = tid + i * 256;
        int tile = p >> 9, r = (p >> 2) & 127, cc = p & 3;
        uint32_t dst = sb + tile * TILE16 + r * ROWB + cc * 16;
        const void* src;
        if (tile == 0)      src = &g_x_hi[t][row0 + r][cc * 8];
        else if (tile == 1) src = &g_x_lo[t][row0 + r][cc * 8];
        else if (tile == 2) src = &g_Wih_hi[C0 + r][cc * 8];
        else                src = &g_Wih_lo[C0 + r][cc * 8];
        cpasync16(dst, src);
    }
    asm volatile("cp.async.commit_group;");
    asm volatile("cp.async.wait_group 0;");
    __syncthreads();

    float d[4][4][4];
    #pragma unroll
    for (int a = 0; a < 4; a++)
        #pragma unroll
        for (int b = 0; b < 4; b++)
            #pragma unroll
            for (int c = 0; c < 4; c++) d[a][b][c] = 0.0f;

    const uint32_t b_lane = (wn * 32 + ((lane >> 4) & 1) * 8 + (lane & 7)) * ROWB
                          + ((lane >> 3) & 1) * 16 + 2 * TILE16;
    const uint32_t a_lane = (wm * 64 + (lane & 15)) * ROWB + (lane >> 4) * 16;

    #pragma unroll
    for (int k16 = 0; k16 < 2; k16++) {
        const uint32_t kb = k16 * 32;
        uint32_t bh[4][2], bl[4][2];
        #pragma unroll
        for (int g16 = 0; g16 < 2; g16++) {
            uint32_t ba = sb + b_lane + g16 * (16 * ROWB) + kb;
            uint32_t r4[4];
            ldsm4(r4, ba);
            bh[g16*2+0][0] = r4[0]; bh[g16*2+0][1] = r4[1];
            bh[g16*2+1][0] = r4[2]; bh[g16*2+1][1] = r4[3];
            ldsm4(r4, ba + TILE16);
            bl[g16*2+0][0] = r4[0]; bl[g16*2+0][1] = r4[1];
            bl[g16*2+1][0] = r4[2]; bl[g16*2+1][1] = r4[3];
        }
        uint32_t ah[4][4], al[4][4];
        #pragma unroll
        for (int mf = 0; mf < 4; mf++) {
            uint32_t aa = sb + a_lane + mf * (16 * ROWB) + kb;
            ldsm4(ah[mf], aa);
            ldsm4(al[mf], aa + TILE16);
        }
        #pragma unroll
        for (int mf = 0; mf < 4; mf++)
            #pragma unroll
            for (int nf = 0; nf < 4; nf++) {
                mma16816(d[mf][nf], ah[mf], bh[nf][0], bh[nf][1]);
                mma16816(d[mf][nf], ah[mf], bl[nf][0], bl[nf][1]);
                mma16816(d[mf][nf], al[mf], bh[nf][0], bh[nf][1]);
            }
    }

    float* o = xp + (size_t)blockIdx.z * 2048 * 2048;
    const int g = lane >> 2, tig = lane & 3;
    #pragma unroll
    for (int nf = 0; nf < 4; nf++) {
        int Cc = C0 + wn * 32 + nf * 8 + 2 * tig;
        float b0 = g_bias[Cc], b1 = g_bias[Cc + 1];
        #pragma unroll
        for (int mf = 0; mf < 4; mf++) {
            int rg = row0 + wm * 64 + mf * 16 + g;
            *(float2*)&o[(size_t)rg * 2048 + Cc] =
                make_float2(d[mf][nf][0] + b0, d[mf][nf][1] + b1);
            *(float2*)&o[(size_t)(rg + 8) * 2048 + Cc] =
                make_float2(d[mf][nf][2] + b0, d[mf][nf][3] + b1);
        }
    }
}

// ---- step producer: 3 tiles (Ahi, Whi, Wlo) x 128 rows x 64B / 256 thr ----
__device__ __forceinline__ void produce(uint32_t sb, int st, int kc, int hb,
                                        int row0, int C0, int tid) {
    #pragma unroll
    for (int i = 0; i < 6; i++) {
        int p = tid + i * 256;            // 0..1535
        int tile = p >> 9, r = (p >> 2) & 127, cc = p & 3;
        int ko = kc * 32 + cc * 8;
        uint32_t dst = sb + st * STAGE + tile * TILE + r * ROWB + cc * 16;
        const void* src;
        if (tile == 0)      src = &g_h[hb][row0 + r][ko];
        else if (tile == 1) src = &g_Whi[C0 + r][ko];
        else                src = &g_Wlo[C0 + r][ko];
        cpasync16(dst, src);
    }
}

// ---- LSTM step: 2-term fp16 HMMA + xp epilogue ----
__global__ __launch_bounds__(256, 2) void lstm_step(const float* __restrict__ xp, int t) {
    extern __shared__ __align__(1024) char smem[];
    const uint32_t sb = s2u(smem);
    const int tid = threadIdx.x, wid = tid >> 5, lane = tid & 31;
    const int wm = wid & 1, wn = wid >> 1;
    const int row0 = blockIdx.x * 128, C0 = blockIdx.y * 128;
    const int hb = t & 1, nb = (t + 1) & 1;

    float d[4][4][4];
    #pragma unroll
    for (int a = 0; a < 4; a++)
        #pragma unroll
        for (int b = 0; b < 4; b++)
            #pragma unroll
            for (int c = 0; c < 4; c++) d[a][b][c] = 0.0f;

    produce(sb, 0, 0, hb, row0, C0, tid);
    asm volatile("cp.async.commit_group;");

    const uint32_t b_lane = (wn * 32 + ((lane >> 4) & 1) * 8 + (lane & 7)) * ROWB
                          + ((lane >> 3) & 1) * 16 + TILE;
    const uint32_t a_lane = (wm * 64 + (lane & 15)) * ROWB + (lane >> 4) * 16;

    for (int kc = 0; kc < NCH; kc++) {
        asm volatile("cp.async.wait_group 0;");
        __syncthreads();
        if (kc + 1 < NCH) {
            produce(sb, (kc + 1) & 1, kc + 1, hb, row0, C0, tid);
            asm volatile("cp.async.commit_group;");
        }
        const uint32_t st = sb + (kc & 1) * STAGE;
        #pragma unroll
        for (int k16 = 0; k16 < 2; k16++) {
            const uint32_t kb = k16 * 32;
            uint32_t bh[4][2], bl[4][2];
            #pragma unroll
            for (int g16 = 0; g16 < 2; g16++) {
                uint32_t ba = st + b_lane + g16 * (16 * ROWB) + kb;
                uint32_t r4[4];
                ldsm4(r4, ba);                 // Whi
                bh[g16*2+0][0] = r4[0]; bh[g16*2+0][1] = r4[1];
                bh[g16*2+1][0] = r4[2]; bh[g16*2+1][1] = r4[3];
                ldsm4(r4, ba + TILE);          // Wlo
                bl[g16*2+0][0] = r4[0]; bl[g16*2+0][1] = r4[1];
                bl[g16*2+1][0] = r4[2]; bl[g16*2+1][1] = r4[3];
            }
            uint32_t ah[4][4];
            #pragma unroll
            for (int mf = 0; mf < 4; mf++)
                ldsm4(ah[mf], st + a_lane + mf * (16 * ROWB) + kb);
            #pragma unroll
            for (int mf = 0; mf < 4; mf++)
                #pragma unroll
                for (int nf = 0; nf < 4; nf++)
                    mma16816(d[mf][nf], ah[mf], bh[nf][0], bh[nf][1]);
            #pragma unroll
            for (int mf = 0; mf < 4; mf++)
                #pragma unroll
                for (int nf = 0; nf < 4; nf++)
                    mma16816(d[mf][nf], ah[mf], bl[nf][0], bl[nf][1]);
        }
    }

    // ---- fused epilogue: add xp (incl. bias), gates, c/h update ----
    const int g = lane >> 2, tig = lane & 3;
    #pragma unroll
    for (int nf = 0; nf < 4; nf++) {
        int Cl = wn * 32 + nf * 8 + 2 * tig;
        int j = (C0 >> 2) + wn * 8 + nf * 2 + (tig >> 1);
        #pragma unroll
        for (int mf = 0; mf < 4; mf++) {
            int rl = wm * 64 + mf * 16 + g;
            float2 xp01 = *(const float2*)&xp[(size_t)(row0 + rl) * 2048 + C0 + Cl];
            float2 xp23 = *(const float2*)&xp[(size_t)(row0 + rl + 8) * 2048 + C0 + Cl];
            float c0 = d[mf][nf][0] + xp01.x;
            float c1 = d[mf][nf][1] + xp01.y;
            float c2 = d[mf][nf][2] + xp23.x;
            float c3 = d[mf][nf][3] + xp23.y;
            float s0 = __shfl_xor_sync(0xFFFFFFFFu, c0, 1);
            float sA = __shfl_xor_sync(0xFFFFFFFFu, c1, 1);
            float sB = __shfl_xor_sync(0xFFFFFFFFu, c2, 1);
            float sC = __shfl_xor_sync(0xFFFFFFFFu, c3, 1);
            int row;
            float gi, gf, gg, go;
            if (!(tig & 1)) {
                row = row0 + rl;
                gi = c0; gf = c1; gg = s0; go = sA;
            } else {
                row = row0 + rl + 8;
                gi = sB; gf = sC; gg = c2; go = c3;
            }
            gi = fsig(gi); gf = fsig(gf); gg = ftanh_(gg); go = fsig(go);
            size_t ci = (size_t)j * BB + row;
            float cn = gf * g_c[ci] + gi * gg;
            g_c[ci] = cn;
            g_h[nb][row][j] = __float2half(go * ftanh_(cn));
        }
    }
}

// ---- final FC ----
__global__ void fc_kernel(const float* __restrict__ W_fc,
                          const float* __restrict__ b_fc,
                          float* __restrict__ out)
{
    __shared__ float hs[HH];
    int b = blockIdx.x;
    for (int k = threadIdx.x; k < HH; k += blockDim.x)
        hs[k] = __half2float(g_h[0][b][k]);
    __syncthreads();
    int cls = threadIdx.x;
    if (cls < NC) {
        const float* w = &W_fc[(size_t)cls * HH];
        float acc = 0.0f;
        #pragma unroll 8
        for (int k = 0; k < HH; k++) acc += hs[k] * w[k];
        out[(size_t)b * NC + cls] = acc + b_fc[cls];
    }
}

extern "C" void kernel_launch(void* const* d_in, const int* in_sizes, int n_in,
                              void* d_out, int out_size)
{
    const float* msgs = (const float*)d_in[0];
    const float* W_ih = (const float*)d_in[1];
    const float* W_hh = (const float*)d_in[2];
    const float* b_ih = (const float*)d_in[3];
    const float* b_hh = (const float*)d_in[4];
    const float* W_fc = (const float*)d_in[5];
    const float* b_fc = (const float*)d_in[6];
    float* out = (float*)d_out;

    cudaFuncSetAttribute(xproj_kernel, cudaFuncAttributeMaxDynamicSharedMemorySize, SMEM16);
    cudaFuncSetAttribute(lstm_step, cudaFuncAttributeMaxDynamicSharedMemorySize, SMEMS);

    void *xpA, *xpB;
    cudaGetSymbolAddress(&xpA, g_xpA);
    cudaGetSymbolAddress(&xpB, g_xpB);

    prep_w<<<(2048 * 512 + 255) / 256, 256>>>(W_hh, b_ih, b_hh);
    prep_wih<<<(2048 * 32 + 255) / 256, 256>>>(W_ih);
    prep_x<<<(TT * BB * 32 + 255) / 256, 256>>>(msgs);
    init_state<<<(BB * HH + 255) / 256, 256>>>();

    xproj_kernel<<<dim3(16, 16, 64), 256, SMEM16>>>((float*)xpA, 0);
    xproj_kernel<<<dim3(16, 16, 64), 256, SMEM16>>>((float*)xpB, 64);

    dim3 grid(16, 16);
    for (int t = 0; t < TT; t++) {
        const float* xp_t = (const float*)(t < 64 ? xpA : xpB)
                          + (size_t)(t & 63) * 2048 * 2048;
        lstm_step<<<grid, 256, SMEMS>>>(xp_t, t);
    }
    fc_kernel<<<BB, 128>>>(W_fc, b_fc, out);
}